// round 16
// baseline (speedup 1.0000x reference)
#include <cuda_runtime.h>
#include <cuda_fp16.h>
#include <cstdint>

#define EPSBN 1e-3f
#define WPITCH 132
#define WWORDS (16 * WPITCH)

__device__ __half g_yh[64 * 512 * 128];

__device__ __forceinline__ uint32_t s2u(const void* p) {
    uint32_t a;
    asm("{ .reg .u64 t; cvta.to.shared.u64 t, %1; cvt.u32.u64 %0, t; }" : "=r"(a) : "l"(p));
    return a;
}
__device__ __forceinline__ void cpa16(uint32_t d, const void* s, uint32_t sz) {
    asm volatile("cp.async.cg.shared.global [%0], [%1], 16, %2;"
                 :: "r"(d), "l"(s), "r"(sz) : "memory");
}
__device__ __forceinline__ void cpa16_ef(uint32_t d, const void* s) {
    asm volatile(
        "{\n\t.reg .b64 pol;\n\t"
        "createpolicy.fractional.L2::evict_first.b64 pol, 1.0;\n\t"
        "cp.async.cg.shared.global.L2::cache_hint [%0], [%1], 16, pol;\n\t}"
        :: "r"(d), "l"(s) : "memory");
}
__device__ __forceinline__ void l2pf(const void* p) {
    asm volatile("prefetch.global.L2 [%0];" :: "l"(p));
}
__device__ __forceinline__ void cpcommit() { asm volatile("cp.async.commit_group;" ::: "memory"); }
template <int N> __device__ __forceinline__ void cpwait() {
    asm volatile("cp.async.wait_group %0;" :: "n"(N) : "memory");
}
__device__ __forceinline__ uint32_t packh2(float lo, float hi) {
    __half2 h = __floats2half2_rn(lo, hi);
    return *(uint32_t*)&h;
}
__device__ __forceinline__ void mma16(float* d, const uint32_t* a, const uint32_t* b) {
    asm volatile(
        "mma.sync.aligned.m16n8k16.row.col.f32.f16.f16.f32 "
        "{%0,%1,%2,%3}, {%4,%5,%6,%7}, {%8,%9}, {%0,%1,%2,%3};"
        : "+f"(d[0]), "+f"(d[1]), "+f"(d[2]), "+f"(d[3])
        : "r"(a[0]), "r"(a[1]), "r"(a[2]), "r"(a[3]), "r"(b[0]), "r"(b[1]));
}
__device__ __forceinline__ void ldsm4(uint32_t* a, uint32_t addr) {
    asm volatile("ldmatrix.sync.aligned.m8n8.x4.shared.b16 {%0,%1,%2,%3}, [%4];"
                 : "=r"(a[0]), "=r"(a[1]), "=r"(a[2]), "=r"(a[3]) : "r"(addr));
}
// B fragments for a 32-wide f-slice (nt=4)
__device__ __forceinline__ void loadB4(const float* smW, int tg, int wcol, uint32_t* b) {
    const float* wp = smW + tg * 2 * WPITCH + wcol;
#pragma unroll
    for (int nt = 0; nt < 4; nt++) {
        b[2 * nt]     = packh2(wp[nt * 8], wp[WPITCH + nt * 8]);
        b[2 * nt + 1] = packh2(wp[8 * WPITCH + nt * 8], wp[9 * WPITCH + nt * 8]);
    }
}
// B fragments for a 16-wide f-slice (nt=2)
__device__ __forceinline__ void loadB2(const float* smW, int tg, int wcol, uint32_t* b) {
    const float* wp = smW + tg * 2 * WPITCH + wcol;
#pragma unroll
    for (int nt = 0; nt < 2; nt++) {
        b[2 * nt]     = packh2(wp[nt * 8], wp[WPITCH + nt * 8]);
        b[2 * nt + 1] = packh2(wp[8 * WPITCH + nt * 8], wp[9 * WPITCH + nt * 8]);
    }
}

// ============================================================================
// Stage 1: Conv1D(K=7, SAME) + BN1 + ReLU -> g_yh  (round-14 proven config)
// ============================================================================
#define CAW (128 * 12)
#define CBW (CAW + WWORDS)
#define CONV_SMEM (4 * CBW * 4)

__global__ __launch_bounds__(256, 2) void conv_tc(
    const float* __restrict__ x, const float* __restrict__ w,
    const float* __restrict__ cb,
    const float* __restrict__ g1, const float* __restrict__ b1,
    const float* __restrict__ m1, const float* __restrict__ v1,
    const float* __restrict__ lw) {
    extern __shared__ uint32_t As[];
    const int tid = threadIdx.x;
    const int b = blockIdx.y, l0 = blockIdx.x * 128;
    const int off0 = (l0 - 3) * 64;
    const float* xb = x + (size_t)b * 32768;
    const uint32_t smb = s2u(As);
    const int bid = blockIdx.x + 4 * blockIdx.y;
    const float* pf = (bid < 212) ? lw + (size_t)bid * 114688 : nullptr;

    auto stage = [&](int c) {
        const int kc = c * 16;
        const uint32_t bb = smb + (uint32_t)((c & 3) * CBW) * 4u;
#pragma unroll
        for (int q = 0; q < 2; q++) {
            const int idx = tid + 256 * q;
            const int m = idx >> 2, j4 = idx & 3;
            const int e = off0 + m * 64 + kc + j4 * 4;
            float4 v = make_float4(0.f, 0.f, 0.f, 0.f);
            if ((unsigned)e < 32768u) v = *(const float4*)&xb[e];
            asm volatile("st.shared.v2.b32 [%0], {%1,%2};"
                         :: "r"(bb + (uint32_t)(m * 12 + j4 * 2) * 4u),
                            "r"(packh2(v.x, v.y)), "r"(packh2(v.z, v.w)) : "memory");
        }
        const uint32_t wb = bb + (uint32_t)CAW * 4u;
#pragma unroll
        for (int q = 0; q < 2; q++) {
            const int idx = tid + 256 * q;
            const int row = idx >> 5, c4 = idx & 31;
            cpa16(wb + (uint32_t)(row * WPITCH + c4 * 4) * 4u,
                  w + (size_t)(kc + row) * 128 + c4 * 4, 16u);
        }
        cpcommit();
    };

    const int wid = tid >> 5, lane = tid & 31;
    const int wg = wid >> 2, wi = wid & 3;
    const int gp = lane >> 2, tg = lane & 3;
    const uint32_t aoff = (uint32_t)(((lane & 15) + wg * 64) * 12 + (lane >> 4) * 4) * 4u;
    float acc[4][4][4] = {};

    stage(0); stage(1); stage(2);
    for (int c = 0; c < 28; c++) {
        if (c + 3 < 28)       { stage(c + 3); cpwait<3>(); }
        else if (c + 3 == 28) { cpwait<2>(); }
        else if (c + 2 == 28) { cpwait<1>(); }
        else                  { cpwait<0>(); }
        if (pf && tid < 128) l2pf(pf + (size_t)(c * 128 + tid) * 32);
        __syncthreads();
        const uint32_t bufb = smb + (uint32_t)((c & 3) * CBW) * 4u;
        const float* smW = (const float*)(As + (c & 3) * CBW + CAW);
        uint32_t bfr[8];
        loadB4(smW, tg, wi * 32 + gp, bfr);
#pragma unroll
        for (int mt = 0; mt < 4; mt++) {
            uint32_t a[4];
            ldsm4(a, bufb + aoff + (uint32_t)(mt * 16 * 48));
#pragma unroll
            for (int nt = 0; nt < 4; nt++) mma16(acc[mt][nt], a, bfr + 2 * nt);
        }
        __syncthreads();
    }

#pragma unroll
    for (int nt = 0; nt < 4; nt++) {
        const int f = wi * 32 + nt * 8 + tg * 2;
        const float s0 = g1[f] * rsqrtf(v1[f] + EPSBN);
        const float s1 = g1[f + 1] * rsqrtf(v1[f + 1] + EPSBN);
        const float h0 = (cb[f] - m1[f]) * s0 + b1[f];
        const float h1 = (cb[f + 1] - m1[f + 1]) * s1 + b1[f + 1];
#pragma unroll
        for (int mt = 0; mt < 4; mt++) {
#pragma unroll
            for (int hr = 0; hr < 2; hr++) {
                const int l = l0 + wg * 64 + mt * 16 + gp + hr * 8;
                const float y0 = fmaxf(fmaf(acc[mt][nt][hr * 2], s0, h0), 0.f);
                const float y1 = fmaxf(fmaf(acc[mt][nt][hr * 2 + 1], s1, h1), 0.f);
                *(uint32_t*)&g_yh[(size_t)b * 65536 + (size_t)l * 128 + f] = packh2(y0, y1);
            }
        }
    }
}

// ============================================================================
// Stage 2: LocallyConnected1D(K=7, VALID) + BN2 + ReLU
// 256 thr / 8 warps (f-slice 16 per warp, nt=2) -> 24 warps/SM at 3 blocks.
// Same NBUF=4 k16 pipeline, pitch-132 W, evict_first, ldmatrix A.
// ============================================================================
#define LAW (64 * 12)
#define LBW (LAW + WWORDS)          // 2880 words = 11520 B

__global__ __launch_bounds__(256, 3) void local_tc(
    const float* __restrict__ lw, const float* __restrict__ lb,
    const float* __restrict__ g2, const float* __restrict__ b2,
    const float* __restrict__ m2, const float* __restrict__ v2,
    float* __restrict__ out) {
    __shared__ uint32_t As[4 * LBW];
    const int tid = threadIdx.x;
    const int l = blockIdx.x;
    const float* W = lw + (size_t)l * 114688;
    const uint32_t smb = s2u(As);
    const int wid = tid >> 5, lane = tid & 31;
    const int gp = lane >> 2, tg = lane & 3;
    const uint32_t aoff = (uint32_t)((lane & 15) * 12 + (lane >> 4) * 4) * 4u;

    auto stage = [&](int c) {
        const uint32_t bb = smb + (uint32_t)((c & 3) * LBW) * 4u;
        if (tid < 128) {  // A: 64 rows x 16 k fp16 = 128 x 16B
            const int m = tid >> 1, h = tid & 1;
            const int so = m * 65536 + l * 128 + c * 16 + h * 8;
            cpa16(bb + (uint32_t)(m * 12 + h * 4) * 4u,
                  (const char*)g_yh + (size_t)so * 2, 16u);
        }
        const uint32_t wb = bb + (uint32_t)LAW * 4u;
#pragma unroll
        for (int q = 0; q < 2; q++) {  // W: 512 x 16B over 256 threads
            const int idx = tid + 256 * q;
            const int row = idx >> 5, c4 = idx & 31;
            cpa16_ef(wb + (uint32_t)(row * WPITCH + c4 * 4) * 4u,
                     W + (size_t)(c * 16 + row) * 128 + c4 * 4);
        }
        cpcommit();
    };

    float acc[4][2][4] = {};
    stage(0); stage(1); stage(2);
    for (int c = 0; c < 56; c++) {
        if (c + 3 < 56)       { stage(c + 3); cpwait<3>(); }
        else if (c + 3 == 56) { cpwait<2>(); }
        else if (c + 2 == 56) { cpwait<1>(); }
        else                  { cpwait<0>(); }
        __syncthreads();
        const uint32_t bufb = smb + (uint32_t)((c & 3) * LBW) * 4u;
        const float* smW = (const float*)(As + (c & 3) * LBW + LAW);
        uint32_t bfr[4];
        loadB2(smW, tg, wid * 16 + gp, bfr);
#pragma unroll
        for (int mt = 0; mt < 4; mt++) {
            uint32_t a[4];
            ldsm4(a, bufb + aoff + (uint32_t)(mt * 16 * 48));
#pragma unroll
            for (int nt = 0; nt < 2; nt++) mma16(acc[mt][nt], a, bfr + 2 * nt);
        }
        __syncthreads();
    }

#pragma unroll
    for (int nt = 0; nt < 2; nt++) {
        const int f = wid * 16 + nt * 8 + tg * 2;
        const float s0 = g2[f] * rsqrtf(v2[f] + EPSBN);
        const float s1 = g2[f + 1] * rsqrtf(v2[f + 1] + EPSBN);
        const float h0 = (lb[l * 128 + f] - m2[f]) * s0 + b2[f];
        const float h1 = (lb[l * 128 + f + 1] - m2[f + 1]) * s1 + b2[f + 1];
#pragma unroll
        for (int mt = 0; mt < 4; mt++) {
#pragma unroll
            for (int hr = 0; hr < 2; hr++) {
                const int bat = mt * 16 + gp + hr * 8;
                float2 r;
                r.x = fmaxf(fmaf(acc[mt][nt][hr * 2], s0, h0), 0.f);
                r.y = fmaxf(fmaf(acc[mt][nt][hr * 2 + 1], s1, h1), 0.f);
                *(float2*)&out[(size_t)bat * 506 * 128 + (size_t)l * 128 + f] = r;
            }
        }
    }
}

extern "C" void kernel_launch(void* const* d_in, const int* in_sizes, int n_in,
                              void* d_out, int out_size) {
    const float* x      = (const float*)d_in[0];
    const float* conv_w = (const float*)d_in[1];
    const float* conv_b = (const float*)d_in[2];
    const float* g1     = (const float*)d_in[3];
    const float* b1     = (const float*)d_in[4];
    const float* m1     = (const float*)d_in[5];
    const float* v1     = (const float*)d_in[6];
    const float* lw     = (const float*)d_in[7];
    const float* lb     = (const float*)d_in[8];
    const float* g2     = (const float*)d_in[9];
    const float* b2     = (const float*)d_in[10];
    const float* m2     = (const float*)d_in[11];
    const float* v2     = (const float*)d_in[12];
    float* out = (float*)d_out;

    cudaFuncSetAttribute(conv_tc, cudaFuncAttributeMaxDynamicSharedMemorySize, CONV_SMEM);

    conv_tc<<<dim3(4, 64), 256, CONV_SMEM>>>(x, conv_w, conv_b, g1, b1, m1, v1, lw);
    local_tc<<<506, 256>>>(lw, lb, g2, b2, m2, v2, out);
}

// round 17
// speedup vs baseline: 1.1656x; 1.1656x over previous
#include <cuda_runtime.h>
#include <cuda_fp16.h>
#include <cstdint>

#define EPSBN 1e-3f
#define WPITCH 132
#define WWORDS (16 * WPITCH)

__device__ __half g_yh[64 * 512 * 128];

__device__ __forceinline__ uint32_t s2u(const void* p) {
    uint32_t a;
    asm("{ .reg .u64 t; cvta.to.shared.u64 t, %1; cvt.u32.u64 %0, t; }" : "=r"(a) : "l"(p));
    return a;
}
__device__ __forceinline__ void cpa16(uint32_t d, const void* s, uint32_t sz) {
    asm volatile("cp.async.cg.shared.global [%0], [%1], 16, %2;"
                 :: "r"(d), "l"(s), "r"(sz) : "memory");
}
__device__ __forceinline__ void cpa16_ef(uint32_t d, const void* s) {
    asm volatile(
        "{\n\t.reg .b64 pol;\n\t"
        "createpolicy.fractional.L2::evict_first.b64 pol, 1.0;\n\t"
        "cp.async.cg.shared.global.L2::cache_hint [%0], [%1], 16, pol;\n\t}"
        :: "r"(d), "l"(s) : "memory");
}
__device__ __forceinline__ void l2pf(const void* p) {
    asm volatile("prefetch.global.L2 [%0];" :: "l"(p));
}
__device__ __forceinline__ void cpcommit() { asm volatile("cp.async.commit_group;" ::: "memory"); }
template <int N> __device__ __forceinline__ void cpwait() {
    asm volatile("cp.async.wait_group %0;" :: "n"(N) : "memory");
}
__device__ __forceinline__ uint32_t packh2(float lo, float hi) {
    __half2 h = __floats2half2_rn(lo, hi);
    return *(uint32_t*)&h;
}
__device__ __forceinline__ void mma16(float* d, const uint32_t* a, const uint32_t* b) {
    asm volatile(
        "mma.sync.aligned.m16n8k16.row.col.f32.f16.f16.f32 "
        "{%0,%1,%2,%3}, {%4,%5,%6,%7}, {%8,%9}, {%0,%1,%2,%3};"
        : "+f"(d[0]), "+f"(d[1]), "+f"(d[2]), "+f"(d[3])
        : "r"(a[0]), "r"(a[1]), "r"(a[2]), "r"(a[3]), "r"(b[0]), "r"(b[1]));
}
__device__ __forceinline__ void ldsm4(uint32_t* a, uint32_t addr) {
    asm volatile("ldmatrix.sync.aligned.m8n8.x4.shared.b16 {%0,%1,%2,%3}, [%4];"
                 : "=r"(a[0]), "=r"(a[1]), "=r"(a[2]), "=r"(a[3]) : "r"(addr));
}
__device__ __forceinline__ void loadB4(const float* smW, int tg, int wcol, uint32_t* b) {
    const float* wp = smW + tg * 2 * WPITCH + wcol;
#pragma unroll
    for (int nt = 0; nt < 4; nt++) {
        b[2 * nt]     = packh2(wp[nt * 8], wp[WPITCH + nt * 8]);
        b[2 * nt + 1] = packh2(wp[8 * WPITCH + nt * 8], wp[9 * WPITCH + nt * 8]);
    }
}

// ============================================================================
// Stage 1: Conv1D(K=7, SAME) + BN1 + ReLU -> g_yh  (round-14/15 proven config)
// ============================================================================
#define CAW (128 * 12)
#define CBW (CAW + WWORDS)
#define CONV_SMEM (4 * CBW * 4)

__global__ __launch_bounds__(256, 2) void conv_tc(
    const float* __restrict__ x, const float* __restrict__ w,
    const float* __restrict__ cb,
    const float* __restrict__ g1, const float* __restrict__ b1,
    const float* __restrict__ m1, const float* __restrict__ v1,
    const float* __restrict__ lw) {
    extern __shared__ uint32_t As[];
    const int tid = threadIdx.x;
    const int b = blockIdx.y, l0 = blockIdx.x * 128;
    const int off0 = (l0 - 3) * 64;
    const float* xb = x + (size_t)b * 32768;
    const uint32_t smb = s2u(As);
    const int bid = blockIdx.x + 4 * blockIdx.y;
    const float* pf = (bid < 212) ? lw + (size_t)bid * 114688 : nullptr;

    auto stage = [&](int c) {
        const int kc = c * 16;
        const uint32_t bb = smb + (uint32_t)((c & 3) * CBW) * 4u;
#pragma unroll
        for (int q = 0; q < 2; q++) {
            const int idx = tid + 256 * q;
            const int m = idx >> 2, j4 = idx & 3;
            const int e = off0 + m * 64 + kc + j4 * 4;
            float4 v = make_float4(0.f, 0.f, 0.f, 0.f);
            if ((unsigned)e < 32768u) v = *(const float4*)&xb[e];
            asm volatile("st.shared.v2.b32 [%0], {%1,%2};"
                         :: "r"(bb + (uint32_t)(m * 12 + j4 * 2) * 4u),
                            "r"(packh2(v.x, v.y)), "r"(packh2(v.z, v.w)) : "memory");
        }
        const uint32_t wb = bb + (uint32_t)CAW * 4u;
#pragma unroll
        for (int q = 0; q < 2; q++) {
            const int idx = tid + 256 * q;
            const int row = idx >> 5, c4 = idx & 31;
            cpa16(wb + (uint32_t)(row * WPITCH + c4 * 4) * 4u,
                  w + (size_t)(kc + row) * 128 + c4 * 4, 16u);
        }
        cpcommit();
    };

    const int wid = tid >> 5, lane = tid & 31;
    const int wg = wid >> 2, wi = wid & 3;
    const int gp = lane >> 2, tg = lane & 3;
    const uint32_t aoff = (uint32_t)(((lane & 15) + wg * 64) * 12 + (lane >> 4) * 4) * 4u;
    float acc[4][4][4] = {};

    stage(0); stage(1); stage(2);
    for (int c = 0; c < 28; c++) {
        if (c + 3 < 28)       { stage(c + 3); cpwait<3>(); }
        else if (c + 3 == 28) { cpwait<2>(); }
        else if (c + 2 == 28) { cpwait<1>(); }
        else                  { cpwait<0>(); }
        if (pf && tid < 128) l2pf(pf + (size_t)(c * 128 + tid) * 32);
        __syncthreads();
        const uint32_t bufb = smb + (uint32_t)((c & 3) * CBW) * 4u;
        const float* smW = (const float*)(As + (c & 3) * CBW + CAW);
        uint32_t bfr[8];
        loadB4(smW, tg, wi * 32 + gp, bfr);
#pragma unroll
        for (int mt = 0; mt < 4; mt++) {
            uint32_t a[4];
            ldsm4(a, bufb + aoff + (uint32_t)(mt * 16 * 48));
#pragma unroll
            for (int nt = 0; nt < 4; nt++) mma16(acc[mt][nt], a, bfr + 2 * nt);
        }
        __syncthreads();
    }

#pragma unroll
    for (int nt = 0; nt < 4; nt++) {
        const int f = wi * 32 + nt * 8 + tg * 2;
        const float s0 = g1[f] * rsqrtf(v1[f] + EPSBN);
        const float s1 = g1[f + 1] * rsqrtf(v1[f + 1] + EPSBN);
        const float h0 = (cb[f] - m1[f]) * s0 + b1[f];
        const float h1 = (cb[f + 1] - m1[f + 1]) * s1 + b1[f + 1];
#pragma unroll
        for (int mt = 0; mt < 4; mt++) {
#pragma unroll
            for (int hr = 0; hr < 2; hr++) {
                const int l = l0 + wg * 64 + mt * 16 + gp + hr * 8;
                const float y0 = fmaxf(fmaf(acc[mt][nt][hr * 2], s0, h0), 0.f);
                const float y1 = fmaxf(fmaf(acc[mt][nt][hr * 2 + 1], s1, h1), 0.f);
                *(uint32_t*)&g_yh[(size_t)b * 65536 + (size_t)l * 128 + f] = packh2(y0, y1);
            }
        }
    }
}

// ============================================================================
// Stage 2: LocallyConnected1D(K=7, VALID) + BN2 + ReLU
// 128 thr / 4 warps, M=64, k16 chunks. NBUF=5, 4 chunks in flight, still
// 4 blocks/SM: A stored UNPADDED (64x8 words) with 16B-segment XOR swizzle
// (seg' = seg ^ ((row>>2)&1)) -- conflict-free for both cp.async stores and
// ldmatrix 8-row phases. Buffer 10496 B; 5 buffers = 52.5 KB < 57 KB.
// ============================================================================
#define LAW 512                      // A words per buffer (64 rows x 8 words)
#define LBW (LAW + WWORDS)           // 2624 words = 10496 B
#define LNBUF 5
#define LOCAL_SMEM (LNBUF * LBW * 4) // 52480 B

__global__ __launch_bounds__(128, 4) void local_tc(
    const float* __restrict__ lw, const float* __restrict__ lb,
    const float* __restrict__ g2, const float* __restrict__ b2,
    const float* __restrict__ m2, const float* __restrict__ v2,
    float* __restrict__ out) {
    extern __shared__ uint32_t As[];
    const int tid = threadIdx.x;
    const int l = blockIdx.x;
    const float* W = lw + (size_t)l * 114688;
    const uint32_t smb = s2u(As);
    const int wid = tid >> 5, lane = tid & 31;
    const int gp = lane >> 2, tg = lane & 3;
    // ldmatrix lane offset with segment swizzle: row r=lane&15, seg=(lane>>4)^((r>>2)&1)
    const uint32_t aoff = (uint32_t)(((lane & 15) * 8 +
                                      (((lane >> 4) ^ ((lane >> 2) & 1)) * 4)) * 4);

    auto stage = [&](int c) {
        const uint32_t bb = smb + (uint32_t)((c % LNBUF) * LBW) * 4u;
        {   // A: 64 rows x 16 k fp16; seg-swizzled store
            const int m = tid >> 1, h = tid & 1;
            const int seg = h ^ ((m >> 2) & 1);
            const int so = m * 65536 + l * 128 + c * 16 + h * 8;
            cpa16(bb + (uint32_t)(m * 8 + seg * 4) * 4u,
                  (const char*)g_yh + (size_t)so * 2, 16u);
        }
        const uint32_t wb = bb + (uint32_t)LAW * 4u;
#pragma unroll
        for (int q = 0; q < 4; q++) {
            const int idx = tid + 128 * q;
            const int row = idx >> 5, c4 = idx & 31;
            cpa16_ef(wb + (uint32_t)(row * WPITCH + c4 * 4) * 4u,
                     W + (size_t)(c * 16 + row) * 128 + c4 * 4);
        }
        cpcommit();
    };

    float acc[4][4][4] = {};
    stage(0); stage(1); stage(2); stage(3);
    for (int c = 0; c < 56; c++) {
        if (c + 4 < 56)       { stage(c + 4); cpwait<4>(); }
        else if (c + 4 == 56) { cpwait<3>(); }
        else if (c + 3 == 56) { cpwait<2>(); }
        else if (c + 2 == 56) { cpwait<1>(); }
        else                  { cpwait<0>(); }
        __syncthreads();
        const uint32_t bufb = smb + (uint32_t)((c % LNBUF) * LBW) * 4u;
        const float* smW = (const float*)(As + (c % LNBUF) * LBW + LAW);
        uint32_t bfr[8];
        loadB4(smW, tg, wid * 32 + gp, bfr);
#pragma unroll
        for (int mt = 0; mt < 4; mt++) {
            uint32_t a[4];
            // rows mt*16 + r: mt*16*8 words = mt*512 B; swizzle bit unaffected
            ldsm4(a, bufb + aoff + (uint32_t)(mt * 512));
#pragma unroll
            for (int nt = 0; nt < 4; nt++) mma16(acc[mt][nt], a, bfr + 2 * nt);
        }
        __syncthreads();
    }

#pragma unroll
    for (int nt = 0; nt < 4; nt++) {
        const int f = wid * 32 + nt * 8 + tg * 2;
        const float s0 = g2[f] * rsqrtf(v2[f] + EPSBN);
        const float s1 = g2[f + 1] * rsqrtf(v2[f + 1] + EPSBN);
        const float h0 = (lb[l * 128 + f] - m2[f]) * s0 + b2[f];
        const float h1 = (lb[l * 128 + f + 1] - m2[f + 1]) * s1 + b2[f + 1];
#pragma unroll
        for (int mt = 0; mt < 4; mt++) {
#pragma unroll
            for (int hr = 0; hr < 2; hr++) {
                const int bat = mt * 16 + gp + hr * 8;
                float2 r;
                r.x = fmaxf(fmaf(acc[mt][nt][hr * 2], s0, h0), 0.f);
                r.y = fmaxf(fmaf(acc[mt][nt][hr * 2 + 1], s1, h1), 0.f);
                *(float2*)&out[(size_t)bat * 506 * 128 + (size_t)l * 128 + f] = r;
            }
        }
    }
}

extern "C" void kernel_launch(void* const* d_in, const int* in_sizes, int n_in,
                              void* d_out, int out_size) {
    const float* x      = (const float*)d_in[0];
    const float* conv_w = (const float*)d_in[1];
    const float* conv_b = (const float*)d_in[2];
    const float* g1     = (const float*)d_in[3];
    const float* b1     = (const float*)d_in[4];
    const float* m1     = (const float*)d_in[5];
    const float* v1     = (const float*)d_in[6];
    const float* lw     = (const float*)d_in[7];
    const float* lb     = (const float*)d_in[8];
    const float* g2     = (const float*)d_in[9];
    const float* b2     = (const float*)d_in[10];
    const float* m2     = (const float*)d_in[11];
    const float* v2     = (const float*)d_in[12];
    float* out = (float*)d_out;

    cudaFuncSetAttribute(conv_tc, cudaFuncAttributeMaxDynamicSharedMemorySize, CONV_SMEM);
    cudaFuncSetAttribute(local_tc, cudaFuncAttributeMaxDynamicSharedMemorySize, LOCAL_SMEM);

    conv_tc<<<dim3(4, 64), 256, CONV_SMEM>>>(x, conv_w, conv_b, g1, b1, m1, v1, lw);
    local_tc<<<506, 128, LOCAL_SMEM>>>(lw, lb, g2, b2, m2, v2, out);
}